// round 3
// baseline (speedup 1.0000x reference)
#include <cuda_runtime.h>
#include <cuda_bf16.h>
#include <cstdint>

// MaxUnpooling2D scatter-add.
//   updates/mask: [B=16, H=128, W=128, C=64]  -> 16,777,216 elements
//   output:       [B=16, OH=256, OW=256, C=64] -> 67,108,864 floats (268 MB)
// out_idx = (b<<22) | (mask & ~63) | c   (channel comes from the source element)
//
// Strategy: group-of-2-batch L2-resident zero+scatter fusion, with
//   - per-thread MLP: scatter = 2 quads (4 front-batched LDG.128, 8 REDG),
//     zero = 4x float4 stores
//   - scatter/zero blocks interleaved via blk%3 so both traffic types flow
//     on every SM throughout the kernel
//   - 9 total launches instead of 17

static constexpr int B_DIM       = 16;
static constexpr int GROUP       = 2;                    // batches per kernel
static constexpr int NGROUPS     = B_DIM / GROUP;        // 8
static constexpr int HWC         = 128 * 128 * 64;       // 1<<20 elems per batch
static constexpr int OUT_PER_B   = 1 << 22;              // output floats per batch

static constexpr int THREADS     = 256;

// Scatter: GROUP batches -> 524,288 quads; 2 quads/thread -> 1024 blocks.
static constexpr int SQ_PER_B    = HWC / 4;              // 262,144 quads per batch (1<<18)
static constexpr int S_THREADS_T = SQ_PER_B;             // threads cover batch 0 quads; +offset covers batch 1
static constexpr int S_BLOCKS    = S_THREADS_T / THREADS;        // 1024

// Zero: GROUP batches -> 2,097,152 float4; 4 per thread -> 2048 blocks.
static constexpr int Z_VEC4      = GROUP * OUT_PER_B / 4;        // 1<<21
static constexpr int Z_STRIDE    = Z_VEC4 / 4;                   // 524,288 (thread count)
static constexpr int Z_BLOCKS    = Z_STRIDE / THREADS;           // 2048

static constexpr int FUSED_BLOCKS = S_BLOCKS + Z_BLOCKS;         // 3072

// ---------------------------------------------------------------------------
// Scatter 2 batches. upd4/msk4/out pre-offset to the group's start.
// Thread t handles quad t (batch 0 of group) and quad t + SQ_PER_B (batch 1).
__device__ __forceinline__ void scatter_group(const float4* __restrict__ upd4,
                                              const int4*   __restrict__ msk4,
                                              float* __restrict__ out,
                                              int sblk)
{
    int t = sblk * THREADS + threadIdx.x;        // 0 .. 262,143
    int i4a = t;                                  // quad in batch 0 of group
    int i4b = t + SQ_PER_B;                       // quad in batch 1 of group
    int ca  = (i4a << 2) & 63;                    // first-lane channel (same for both: (t<<2)&63)

    // Front-batch all 4 wide loads for MLP.
    float4 ua = __ldg(&upd4[i4a]);
    float4 ub = __ldg(&upd4[i4b]);
    int4   ma = __ldg(&msk4[i4a]);
    int4   mb = __ldg(&msk4[i4b]);

    float* out0 = out;                            // batch 0 region of group
    float* out1 = out + OUT_PER_B;                // batch 1 region of group

    atomicAdd(&out0[(ma.x & ~63) | (ca + 0)], ua.x);
    atomicAdd(&out0[(ma.y & ~63) | (ca + 1)], ua.y);
    atomicAdd(&out0[(ma.z & ~63) | (ca + 2)], ua.z);
    atomicAdd(&out0[(ma.w & ~63) | (ca + 3)], ua.w);

    atomicAdd(&out1[(mb.x & ~63) | (ca + 0)], ub.x);
    atomicAdd(&out1[(mb.y & ~63) | (ca + 1)], ub.y);
    atomicAdd(&out1[(mb.z & ~63) | (ca + 2)], ub.z);
    atomicAdd(&out1[(mb.w & ~63) | (ca + 3)], ub.w);
}

// Zero 2 batches worth of output: 4 float4 per thread, coalesced strided.
__device__ __forceinline__ void zero_group(float4* __restrict__ out4, int zblk)
{
    int t = zblk * THREADS + threadIdx.x;        // 0 .. 524,287
    const float4 z = make_float4(0.f, 0.f, 0.f, 0.f);
    out4[t + 0 * Z_STRIDE] = z;
    out4[t + 1 * Z_STRIDE] = z;
    out4[t + 2 * Z_STRIDE] = z;
    out4[t + 3 * Z_STRIDE] = z;
}

// ---------------------------------------------------------------------------
__global__ void __launch_bounds__(THREADS)
zero_kernel(float4* __restrict__ out4)
{
    zero_group(out4, blockIdx.x);
}

// Fused: scatter group g + zero group g+1. Block roles interleaved:
//   blk % 3 == 0 -> scatter block (1024 of 3072)
//   otherwise    -> zero block    (2048 of 3072)
__global__ void __launch_bounds__(THREADS)
scatter_zero_kernel(const float4* __restrict__ upd4,
                    const int4*   __restrict__ msk4,
                    float* __restrict__ out_g,
                    float4* __restrict__ out4_next)
{
    int blk = blockIdx.x;
    int q = blk / 3, r = blk - 3 * q;
    if (r == 0) {
        scatter_group(upd4, msk4, out_g, q);
    } else {
        zero_group(out4_next, 2 * q + (r - 1));
    }
}

__global__ void __launch_bounds__(THREADS)
scatter_kernel(const float4* __restrict__ upd4,
               const int4*   __restrict__ msk4,
               float* __restrict__ out_g)
{
    scatter_group(upd4, msk4, out_g, blockIdx.x);
}

// ---------------------------------------------------------------------------
extern "C" void kernel_launch(void* const* d_in, const int* in_sizes, int n_in,
                              void* d_out, int out_size)
{
    const float4* upd4 = (const float4*)d_in[0];
    const int4*   msk4 = (const int4*)d_in[1];
    float*        out  = (float*)d_out;

    const size_t GRP_QUADS = (size_t)GROUP * SQ_PER_B;     // input quads per group
    const size_t GRP_OUT   = (size_t)GROUP * OUT_PER_B;    // output floats per group

    // Prologue: zero group 0.
    zero_kernel<<<Z_BLOCKS, THREADS>>>((float4*)out);

    // Steady state: scatter(g) interleaved with zero(g+1).
    for (int g = 0; g < NGROUPS - 1; g++) {
        scatter_zero_kernel<<<FUSED_BLOCKS, THREADS>>>(
            upd4 + (size_t)g * GRP_QUADS,
            msk4 + (size_t)g * GRP_QUADS,
            out  + (size_t)g * GRP_OUT,
            (float4*)(out + (size_t)(g + 1) * GRP_OUT));
    }

    // Epilogue: scatter last group.
    int g = NGROUPS - 1;
    scatter_kernel<<<S_BLOCKS, THREADS>>>(
        upd4 + (size_t)g * GRP_QUADS,
        msk4 + (size_t)g * GRP_QUADS,
        out  + (size_t)g * GRP_OUT);
}

// round 4
// speedup vs baseline: 1.0546x; 1.0546x over previous
#include <cuda_runtime.h>
#include <cuda_bf16.h>
#include <cstdint>

// MaxUnpooling2D scatter-add.
//   updates/mask: [B=16, H=128, W=128, C=64]  -> 16,777,216 elements
//   output:       [B=16, OH=256, OW=256, C=64] -> 67,108,864 floats (268 MB)
// out_idx = (b<<22) | (mask & ~63) | c   (channel comes from the source element)
//
// R4: per-batch (GROUP=1) L2-resident zero+scatter fusion with
//     scatter/zero block-role interleave (1:4) so the REDG atomic stream and
//     the zero-store DRAM stream overlap throughout each kernel, plus
//     per-thread MLP (scatter: 2 quads; zero: 2x float4).

static constexpr int B_DIM      = 16;
static constexpr int HWC        = 128 * 128 * 64;   // 1<<20 elems per batch
static constexpr int OUT_PER_B  = 1 << 22;          // output floats per batch

static constexpr int THREADS    = 256;

// Scatter: 262,144 quads per batch; 2 quads/thread -> 131,072 threads -> 512 blocks.
static constexpr int SQ_PER_B   = HWC / 4;                    // 1<<18 quads
static constexpr int S_TH       = SQ_PER_B / 2;               // 131,072 threads
static constexpr int S_BLOCKS   = S_TH / THREADS;             // 512

// Zero: 1,048,576 float4 per batch; 2/thread -> 524,288 threads -> 2048 blocks.
static constexpr int Z_VEC4     = OUT_PER_B / 4;              // 1<<20
static constexpr int Z_STRIDE   = Z_VEC4 / 2;                 // 524,288 (threads)
static constexpr int Z_BLOCKS   = Z_STRIDE / THREADS;         // 2048

static constexpr int FUSED_BLOCKS = S_BLOCKS + Z_BLOCKS;      // 2560 ; ratio 1:4

// ---------------------------------------------------------------------------
// Scatter one batch; thread handles quads t and t + S_TH (both same batch).
__device__ __forceinline__ void scatter_batch(const float4* __restrict__ upd4,
                                              const int4*   __restrict__ msk4,
                                              float* __restrict__ out,
                                              int sblk)
{
    int t   = sblk * THREADS + threadIdx.x;      // 0 .. 131,071
    int i4a = t;
    int i4b = t + S_TH;
    int ca  = (i4a << 2) & 63;                   // == (i4b<<2)&63 since S_TH<<2 is mult of 64

    // Front-batch all wide loads for MLP.
    float4 ua = __ldg(&upd4[i4a]);
    float4 ub = __ldg(&upd4[i4b]);
    int4   ma = __ldg(&msk4[i4a]);
    int4   mb = __ldg(&msk4[i4b]);

    atomicAdd(&out[(ma.x & ~63) | (ca + 0)], ua.x);
    atomicAdd(&out[(ma.y & ~63) | (ca + 1)], ua.y);
    atomicAdd(&out[(ma.z & ~63) | (ca + 2)], ua.z);
    atomicAdd(&out[(ma.w & ~63) | (ca + 3)], ua.w);

    atomicAdd(&out[(mb.x & ~63) | (ca + 0)], ub.x);
    atomicAdd(&out[(mb.y & ~63) | (ca + 1)], ub.y);
    atomicAdd(&out[(mb.z & ~63) | (ca + 2)], ub.z);
    atomicAdd(&out[(mb.w & ~63) | (ca + 3)], ub.w);
}

// Zero one batch's output region: 2 float4 per thread, coalesced strided.
__device__ __forceinline__ void zero_batch(float4* __restrict__ out4, int zblk)
{
    int t = zblk * THREADS + threadIdx.x;        // 0 .. 524,287
    const float4 z = make_float4(0.f, 0.f, 0.f, 0.f);
    out4[t]            = z;
    out4[t + Z_STRIDE] = z;
}

// ---------------------------------------------------------------------------
__global__ void __launch_bounds__(THREADS)
zero_kernel(float4* __restrict__ out4)
{
    zero_batch(out4, blockIdx.x);
}

// Fused: scatter batch b + zero batch b+1, roles interleaved 1:4.
//   blk % 5 == 0 -> scatter block (512 of 2560)
//   otherwise    -> zero block    (2048 of 2560)
__global__ void __launch_bounds__(THREADS)
scatter_zero_kernel(const float4* __restrict__ upd4,
                    const int4*   __restrict__ msk4,
                    float* __restrict__ out_b,
                    float4* __restrict__ out4_next)
{
    int blk = blockIdx.x;
    int q = blk / 5, r = blk - 5 * q;
    if (r == 0) {
        scatter_batch(upd4, msk4, out_b, q);
    } else {
        zero_batch(out4_next, 4 * q + (r - 1));
    }
}

__global__ void __launch_bounds__(THREADS)
scatter_kernel(const float4* __restrict__ upd4,
               const int4*   __restrict__ msk4,
               float* __restrict__ out_b)
{
    scatter_batch(upd4, msk4, out_b, blockIdx.x);
}

// ---------------------------------------------------------------------------
extern "C" void kernel_launch(void* const* d_in, const int* in_sizes, int n_in,
                              void* d_out, int out_size)
{
    const float4* upd4 = (const float4*)d_in[0];
    const int4*   msk4 = (const int4*)d_in[1];
    float*        out  = (float*)d_out;

    // Prologue: zero batch 0.
    zero_kernel<<<Z_BLOCKS, THREADS>>>((float4*)out);

    // Steady state: scatter(b) interleaved with zero(b+1).
    for (int b = 0; b < B_DIM - 1; b++) {
        scatter_zero_kernel<<<FUSED_BLOCKS, THREADS>>>(
            upd4 + (size_t)b * SQ_PER_B,
            msk4 + (size_t)b * SQ_PER_B,
            out  + (size_t)b * OUT_PER_B,
            (float4*)(out + (size_t)(b + 1) * OUT_PER_B));
    }

    // Epilogue: scatter last batch.
    int b = B_DIM - 1;
    scatter_kernel<<<S_BLOCKS, THREADS>>>(
        upd4 + (size_t)b * SQ_PER_B,
        msk4 + (size_t)b * SQ_PER_B,
        out  + (size_t)b * OUT_PER_B);
}